// round 10
// baseline (speedup 1.0000x reference)
#include <cuda_runtime.h>
#include <cuda_bf16.h>
#include <cstdint>

#define HWTOT 9216
#define NBAT  2
#define CIN   128
#define CE    64
#define BM    64
#define BN    64
#define NITER (HWTOT / BN)   // 144

// ---------------- bf16 split scratch (device globals) ----------------
__device__ __nv_bfloat16 g_Qh[NBAT * HWTOT * CE];   // [n][i][c]
__device__ __nv_bfloat16 g_Ql[NBAT * HWTOT * CE];
__device__ __nv_bfloat16 g_Kh[NBAT * HWTOT * CE];   // [n][j][c]
__device__ __nv_bfloat16 g_Kl[NBAT * HWTOT * CE];
__device__ __nv_bfloat16 g_Vh[NBAT * CIN * HWTOT];  // [n][c][j]
__device__ __nv_bfloat16 g_Vl[NBAT * CIN * HWTOT];

// ---------------- helpers (plain PTX ISA only — no 'a' features) ----------------
__device__ __forceinline__ uint32_t smem_u32(const void* p) {
    uint32_t a;
    asm("{ .reg .u64 t; cvta.to.shared.u64 t, %1; cvt.u32.u64 %0, t; }" : "=r"(a) : "l"(p));
    return a;
}
__device__ __forceinline__ uint32_t swz(uint32_t x) { return x ^ ((x >> 3) & 0x70); }

#define CVT_BF16X2(r, a, b) \
    asm("cvt.rn.satfinite.bf16x2.f32 %0, %1, %2;" : "=r"(r) : "f"(b), "f"(a))  // low=a, high=b

#define CP_ASYNC16(d, s)  asm volatile("cp.async.cg.shared.global [%0], [%1], 16;" :: "r"(d), "l"(s) : "memory")
#define CP_COMMIT()       asm volatile("cp.async.commit_group;" ::: "memory")
#define CP_WAIT0()        asm volatile("cp.async.wait_group 0;" ::: "memory")

#define LDSM4(r0, r1, r2, r3, a) \
    asm volatile("ldmatrix.sync.aligned.m8n8.x4.shared.b16 {%0,%1,%2,%3}, [%4];" \
        : "=r"(r0), "=r"(r1), "=r"(r2), "=r"(r3) : "r"(a) : "memory")

#define MMA_BF16(d, a, b0, b1) \
    asm volatile("mma.sync.aligned.m16n8k16.row.col.f32.bf16.bf16.f32 " \
        "{%0,%1,%2,%3}, {%4,%5,%6,%7}, {%8,%9}, {%0,%1,%2,%3};" \
        : "+f"((d)[0]), "+f"((d)[1]), "+f"((d)[2]), "+f"((d)[3]) \
        : "r"((a)[0]), "r"((a)[1]), "r"((a)[2]), "r"((a)[3]), "r"(b0), "r"(b1))

// ---------------------------------------------------------------------------
// Projection: e1->Qh/Ql [i][c], e2->Kh/Kl [j][c], xa->Vh/Vl [c][j]
// ---------------------------------------------------------------------------
#define PROJ_SMEM ((32 * 128 + 128 * 128) * 4)

__global__ void __launch_bounds__(256, 2) proj_kernel(
    const float* __restrict__ x,
    const float* __restrict__ w1, const float* __restrict__ b1, const float* __restrict__ a1,
    const float* __restrict__ w2, const float* __restrict__ b2, const float* __restrict__ a2,
    const float* __restrict__ wa, const float* __restrict__ ba, const float* __restrict__ aa)
{
    extern __shared__ float sm[];
    float* ws = sm;            // [32][128]
    float* xs = sm + 32 * 128; // compute: [128][128]; staging: [32][132]

    const int n   = blockIdx.z;
    const int rg  = blockIdx.y;
    const int hw0 = blockIdx.x * 128;
    const int tid = threadIdx.x;
    const int rbase = rg * 32;

    const float* W; const float* B; const float* A; int cls;
    if (rbase < 64)       { W = w1 + rbase * CIN;          B = b1 + rbase;          A = a1; cls = 0; }
    else if (rbase < 128) { W = w2 + (rbase - 64) * CIN;   B = b2 + (rbase - 64);   A = a2; cls = 1; }
    else                  { W = wa + (rbase - 128) * CIN;  B = ba + (rbase - 128);  A = aa; cls = 2; }

    for (int idx = tid * 4; idx < 32 * 128; idx += 1024)
        *(float4*)&ws[idx] = *(const float4*)&W[idx];
    for (int idx = tid * 4; idx < 128 * 128; idx += 1024) {
        int c = idx >> 7, h = idx & 127;
        *(float4*)&xs[idx] = *(const float4*)&x[(n * CIN + c) * HWTOT + hw0 + h];
    }
    __syncthreads();

    const int w    = tid >> 5;
    const int lane = tid & 31;

    float acc[4][4];
#pragma unroll
    for (int r = 0; r < 4; r++)
#pragma unroll
        for (int q = 0; q < 4; q++) acc[r][q] = 0.f;

#pragma unroll 4
    for (int c = 0; c < CIN; c++) {
        float4 xv = *(float4*)&xs[c * 128 + 4 * lane];
#pragma unroll
        for (int rr = 0; rr < 4; rr++) {
            float wv = ws[(4 * w + rr) * 128 + c];
            acc[rr][0] += wv * xv.x;
            acc[rr][1] += wv * xv.y;
            acc[rr][2] += wv * xv.z;
            acc[rr][3] += wv * xv.w;
        }
    }

    const float slope = A[0];
    float y[4][4];
#pragma unroll
    for (int rr = 0; rr < 4; rr++) {
        const float bias = B[4 * w + rr];
#pragma unroll
        for (int q = 0; q < 4; q++) {
            float v = acc[rr][q] + bias;
            y[rr][q] = (v >= 0.f) ? v : slope * v;
        }
    }

    if (cls == 2) {
#pragma unroll
        for (int rr = 0; rr < 4; rr++) {
            const int R  = rbase - 128 + 4 * w + rr;
            const int hw = hw0 + 4 * lane;
            uint32_t h01, h23, l01, l23;
            CVT_BF16X2(h01, y[rr][0], y[rr][1]);
            CVT_BF16X2(h23, y[rr][2], y[rr][3]);
            float hf0 = __uint_as_float(h01 << 16), hf1 = __uint_as_float(h01 & 0xffff0000u);
            float hf2 = __uint_as_float(h23 << 16), hf3 = __uint_as_float(h23 & 0xffff0000u);
            CVT_BF16X2(l01, y[rr][0] - hf0, y[rr][1] - hf1);
            CVT_BF16X2(l23, y[rr][2] - hf2, y[rr][3] - hf3);
            size_t off = (size_t)(n * CIN + R) * HWTOT + hw;
            *(uint2*)((char*)g_Vh + off * 2) = make_uint2(h01, h23);
            *(uint2*)((char*)g_Vl + off * 2) = make_uint2(l01, l23);
        }
    } else {
        __syncthreads();
#pragma unroll
        for (int rr = 0; rr < 4; rr++)
#pragma unroll
            for (int q = 0; q < 4; q++)
                xs[(4 * w + rr) * 132 + 4 * lane + q] = y[rr][q];
        __syncthreads();

        const int h    = tid >> 1;
        const int half = tid & 1;
        float f[16];
#pragma unroll
        for (int k = 0; k < 16; k++)
            f[k] = xs[(16 * half + k) * 132 + h];

        uint32_t hp[8], lp[8];
#pragma unroll
        for (int p = 0; p < 8; p++) {
            uint32_t hh;
            CVT_BF16X2(hh, f[2 * p], f[2 * p + 1]);
            float h0 = __uint_as_float(hh << 16);
            float h1 = __uint_as_float(hh & 0xffff0000u);
            uint32_t ll;
            CVT_BF16X2(ll, f[2 * p] - h0, f[2 * p + 1] - h1);
            hp[p] = hh; lp[p] = ll;
        }
        const int col = ((cls == 0) ? rbase : rbase - 64) + 16 * half;
        size_t off = (size_t)(n * HWTOT + hw0 + h) * CE + col;
        __nv_bfloat16* dh = (cls == 0 ? g_Qh : g_Kh) + off;
        __nv_bfloat16* dl = (cls == 0 ? g_Ql : g_Kl) + off;
        *(uint4*)dh       = make_uint4(hp[0], hp[1], hp[2], hp[3]);
        *(uint4*)(dh + 8) = make_uint4(hp[4], hp[5], hp[6], hp[7]);
        *(uint4*)dl       = make_uint4(lp[0], lp[1], lp[2], lp[3]);
        *(uint4*)(dl + 8) = make_uint4(lp[4], lp[5], lp[6], lp[7]);
    }
}

// ---------------------------------------------------------------------------
// mma.sync flash attention, BM=64, 2 CTAs/SM. 8 warps = 4 strips x 2 halves.
// Warp w: QK for strip (w&3), S-cols 32*(w>>2); P via smem;
//         PV for strip (w&3), out-cols 64*(w>>2). o = 32 regs.
// ---------------------------------------------------------------------------
#define OFF_QH 0
#define OFF_QL 8192
#define OFF_KH 16384     // 64j x 64c bf16 = 8192
#define OFF_KL 24576
#define OFF_VH 32768     // 128c x 64j bf16 = 16384
#define OFF_VL 49152
#define OFF_PH 65536     // 64i x 64j bf16 = 8192
#define OFF_PL 73728
#define OFF_LS 81920     // 64 rows x 2 halves x f32 = 512
#define ATTN_SMEM 82432

__global__ void __launch_bounds__(256, 2) attn_kernel(float* __restrict__ out)
{
    extern __shared__ char smem[];
    const uint32_t sb = smem_u32(smem);

    const int n    = blockIdx.y;
    const int i0   = blockIdx.x * BM;
    const int tid  = threadIdx.x;
    const int wid  = tid >> 5;
    const int lane = tid & 31;
    const int strip = wid & 3;       // row strip (16 rows)
    const int half  = wid >> 2;      // 0/1: S-col half (32) and out-col half (64)
    const int m0s   = strip * 16;

    // fragment addressing helpers
    const int mrow = (lane & 7) + ((lane >> 3) & 1) * 8;  // A-frag row
    const int acb  = (lane >> 4) * 16;                    // A-frag k-byte sel
    const int brow = lane & 7;                            // B-frag row
    const int bcb  = (lane >> 3) * 16;                    // B-frag k-byte sel

    // ---- Prologue: Q + K(0) + V(0) ----
    {
        const char* qh = (const char*)g_Qh + (size_t)(n * HWTOT + i0) * CE * 2;
        const char* ql = (const char*)g_Ql + (size_t)(n * HWTOT + i0) * CE * 2;
        for (int i = tid; i < 512; i += 256) {
            CP_ASYNC16(sb + OFF_QH + swz(i * 16), qh + (size_t)i * 16);
            CP_ASYNC16(sb + OFF_QL + swz(i * 16), ql + (size_t)i * 16);
        }
        const char* kh = (const char*)g_Kh + (size_t)(n * HWTOT) * CE * 2;
        const char* kl = (const char*)g_Kl + (size_t)(n * HWTOT) * CE * 2;
        for (int i = tid; i < 512; i += 256) {
            CP_ASYNC16(sb + OFF_KH + swz(i * 16), kh + (size_t)i * 16);
            CP_ASYNC16(sb + OFF_KL + swz(i * 16), kl + (size_t)i * 16);
        }
        const char* vh = (const char*)g_Vh + (size_t)n * CIN * HWTOT * 2;
        const char* vl = (const char*)g_Vl + (size_t)n * CIN * HWTOT * 2;
        for (int i = tid; i < 1024; i += 256) {
            int c = i >> 3, cb = (i & 7) * 16;
            CP_ASYNC16(sb + OFF_VH + swz(i * 16), vh + (size_t)c * HWTOT * 2 + cb);
            CP_ASYNC16(sb + OFF_VL + swz(i * 16), vl + (size_t)c * HWTOT * 2 + cb);
        }
        CP_COMMIT();
    }

    float o[8][4];
#pragma unroll
    for (int i = 0; i < 8; i++)
#pragma unroll
        for (int q = 0; q < 4; q++) o[i][q] = 0.f;
    float lacc0 = 0.f, lacc1 = 0.f;

    for (int t = 0; t < NITER; t++) {
        CP_WAIT0();
        __syncthreads();   // K(t), V(t) resident; P buffer free

        // ---- QK phase: warp computes S[strip, 32*half .. +31] ----
        {
            uint32_t qh[4][4], ql[4][4];
#pragma unroll
            for (int s = 0; s < 4; s++) {
                uint32_t a = sb + OFF_QH + swz((uint32_t)(m0s + mrow) * 128 + s * 32 + acb);
                LDSM4(qh[s][0], qh[s][1], qh[s][2], qh[s][3], a);
                a = sb + OFF_QL + swz((uint32_t)(m0s + mrow) * 128 + s * 32 + acb);
                LDSM4(ql[s][0], ql[s][1], ql[s][2], ql[s][3], a);
            }

#pragma unroll
            for (int nt = 0; nt < 4; nt++) {
                const int jrow = half * 32 + nt * 8;
                uint32_t bh[8], bl[8];
                const uint32_t o0 = swz((uint32_t)(jrow + brow) * 128 + bcb);
                const uint32_t o1 = swz((uint32_t)(jrow + brow) * 128 + bcb + 64);
                LDSM4(bh[0], bh[1], bh[2], bh[3], sb + OFF_KH + o0);
                LDSM4(bh[4], bh[5], bh[6], bh[7], sb + OFF_KH + o1);
                LDSM4(bl[0], bl[1], bl[2], bl[3], sb + OFF_KL + o0);
                LDSM4(bl[4], bl[5], bl[6], bl[7], sb + OFF_KL + o1);

                float sa[4]  = {0.f, 0.f, 0.f, 0.f};
                float sb2[4] = {0.f, 0.f, 0.f, 0.f};
                float sc2[4] = {0.f, 0.f, 0.f, 0.f};
#pragma unroll
                for (int ks = 0; ks < 4; ks++) {
                    MMA_BF16(sa,  qh[ks], bh[2 * ks], bh[2 * ks + 1]);
                    MMA_BF16(sb2, qh[ks], bl[2 * ks], bl[2 * ks + 1]);
                    MMA_BF16(sc2, ql[ks], bh[2 * ks], bh[2 * ks + 1]);
                }
                float e0 = __expf(sa[0] + sb2[0] + sc2[0]);
                float e1 = __expf(sa[1] + sb2[1] + sc2[1]);
                float e2 = __expf(sa[2] + sb2[2] + sc2[2]);
                float e3 = __expf(sa[3] + sb2[3] + sc2[3]);
                lacc0 += e0 + e1;
                lacc1 += e2 + e3;
                uint32_t h01, h23;
                CVT_BF16X2(h01, e0, e1);
                CVT_BF16X2(h23, e2, e3);
                float r0 = e0 - __uint_as_float(h01 << 16);
                float r1 = e1 - __uint_as_float(h01 & 0xffff0000u);
                float r2 = e2 - __uint_as_float(h23 << 16);
                float r3 = e3 - __uint_as_float(h23 & 0xffff0000u);
                uint32_t l01, l23;
                CVT_BF16X2(l01, r0, r1);
                CVT_BF16X2(l23, r2, r3);

                // store P: row = m0s + (lane>>2) (+8), bytecol = 2*j
                const uint32_t pc = (uint32_t)(half * 64 + nt * 16 + (lane & 3) * 4);
                const uint32_t ra = (uint32_t)(m0s + (lane >> 2)) * 128 + pc;
                const uint32_t rb = ra + 8 * 128;
                *(uint32_t*)(smem + OFF_PH + swz(ra)) = h01;
                *(uint32_t*)(smem + OFF_PH + swz(rb)) = h23;
                *(uint32_t*)(smem + OFF_PL + swz(ra)) = l01;
                *(uint32_t*)(smem + OFF_PL + swz(rb)) = l23;
            }
        }
        __syncthreads();   // P visible to partner warp; K buffer free

        // Prefetch K(t+1)
        if (t + 1 < NITER) {
            const int j1 = (t + 1) * BN;
            const char* kh = (const char*)g_Kh + (size_t)(n * HWTOT + j1) * CE * 2;
            const char* kl = (const char*)g_Kl + (size_t)(n * HWTOT + j1) * CE * 2;
            for (int i = tid; i < 512; i += 256) {
                CP_ASYNC16(sb + OFF_KH + swz(i * 16), kh + (size_t)i * 16);
                CP_ASYNC16(sb + OFF_KL + swz(i * 16), kl + (size_t)i * 16);
            }
            CP_COMMIT();
        }

        // ---- PV phase: O[strip, 64*half .. +63] += P[strip,:] V[:,cols] ----
        {
            uint32_t ph[4][4], pl[4][4];
#pragma unroll
            for (int ks = 0; ks < 4; ks++) {
                uint32_t a = sb + OFF_PH + swz((uint32_t)(m0s + mrow) * 128 + ks * 32 + acb);
                LDSM4(ph[ks][0], ph[ks][1], ph[ks][2], ph[ks][3], a);
                a = sb + OFF_PL + swz((uint32_t)(m0s + mrow) * 128 + ks * 32 + acb);
                LDSM4(pl[ks][0], pl[ks][1], pl[ks][2], pl[ks][3], a);
            }
#pragma unroll
            for (int nt2 = 0; nt2 < 8; nt2++) {
                const int crow = half * 64 + nt2 * 8;
                uint32_t vh[8], vl[8];
                const uint32_t o0 = swz((uint32_t)(crow + brow) * 128 + bcb);
                const uint32_t o1 = swz((uint32_t)(crow + brow) * 128 + bcb + 64);
                LDSM4(vh[0], vh[1], vh[2], vh[3], sb + OFF_VH + o0);
                LDSM4(vh[4], vh[5], vh[6], vh[7], sb + OFF_VH + o1);
                LDSM4(vl[0], vl[1], vl[2], vl[3], sb + OFF_VL + o0);
                LDSM4(vl[4], vl[5], vl[6], vl[7], sb + OFF_VL + o1);
#pragma unroll
                for (int ks = 0; ks < 4; ks++) {
                    MMA_BF16(o[nt2], ph[ks], vh[2 * ks], vh[2 * ks + 1]);
                    MMA_BF16(o[nt2], ph[ks], vl[2 * ks], vl[2 * ks + 1]);
                    MMA_BF16(o[nt2], pl[ks], vh[2 * ks], vh[2 * ks + 1]);
                }
            }
        }
        __syncthreads();   // PV done; V buffer free

        // Prefetch V(t+1)
        if (t + 1 < NITER) {
            const int j1 = (t + 1) * BN;
            const char* vh = (const char*)g_Vh + ((size_t)n * CIN * HWTOT + j1) * 2;
            const char* vl = (const char*)g_Vl + ((size_t)n * CIN * HWTOT + j1) * 2;
            for (int i = tid; i < 1024; i += 256) {
                int c = i >> 3, cb = (i & 7) * 16;
                CP_ASYNC16(sb + OFF_VH + swz(i * 16), vh + (size_t)c * HWTOT * 2 + cb);
                CP_ASYNC16(sb + OFF_VL + swz(i * 16), vl + (size_t)c * HWTOT * 2 + cb);
            }
            CP_COMMIT();
        }
    }

    // ---- Epilogue: combine row sums across the two halves ----
    lacc0 += __shfl_xor_sync(0xffffffffu, lacc0, 1);
    lacc0 += __shfl_xor_sync(0xffffffffu, lacc0, 2);
    lacc1 += __shfl_xor_sync(0xffffffffu, lacc1, 1);
    lacc1 += __shfl_xor_sync(0xffffffffu, lacc1, 2);
    float* ls = (float*)(smem + OFF_LS);
    if ((lane & 3) == 0) {
        ls[(m0s + (lane >> 2)) * 2 + half]     = lacc0;
        ls[(m0s + (lane >> 2) + 8) * 2 + half] = lacc1;
    }
    __syncthreads();
    const int r0 = m0s + (lane >> 2);
    const float inv0 = 1.f / (ls[r0 * 2] + ls[r0 * 2 + 1]);
    const float inv1 = 1.f / (ls[(r0 + 8) * 2] + ls[(r0 + 8) * 2 + 1]);

#pragma unroll
    for (int nt2 = 0; nt2 < 8; nt2++) {
        const int c = half * 64 + nt2 * 8 + (lane & 3) * 2;
        const int gi = i0 + r0;
        out[(size_t)(n * CIN + c) * HWTOT + gi]         = o[nt2][0] * inv0;
        out[(size_t)(n * CIN + c + 1) * HWTOT + gi]     = o[nt2][1] * inv0;
        out[(size_t)(n * CIN + c) * HWTOT + gi + 8]     = o[nt2][2] * inv1;
        out[(size_t)(n * CIN + c + 1) * HWTOT + gi + 8] = o[nt2][3] * inv1;
    }
}

extern "C" void kernel_launch(void* const* d_in, const int* in_sizes, int n_in,
                              void* d_out, int out_size)
{
    const float* x  = (const float*)d_in[0];
    const float* w1 = (const float*)d_in[1];
    const float* b1 = (const float*)d_in[2];
    const float* a1 = (const float*)d_in[3];
    const float* w2 = (const float*)d_in[4];
    const float* b2 = (const float*)d_in[5];
    const float* a2 = (const float*)d_in[6];
    const float* wa = (const float*)d_in[7];
    const float* ba = (const float*)d_in[8];
    const float* aa = (const float*)d_in[9];
    float* out = (float*)d_out;

    cudaFuncSetAttribute(proj_kernel, cudaFuncAttributeMaxDynamicSharedMemorySize, PROJ_SMEM);
    cudaFuncSetAttribute(attn_kernel, cudaFuncAttributeMaxDynamicSharedMemorySize, ATTN_SMEM);

    proj_kernel<<<dim3(HWTOT / 128, 8, NBAT), 256, PROJ_SMEM>>>(
        x, w1, b1, a1, w2, b2, a2, wa, ba, aa);
    attn_kernel<<<dim3(HWTOT / BM, NBAT), 256, ATTN_SMEM>>>(out);
}

// round 16
// speedup vs baseline: 1.1289x; 1.1289x over previous
#include <cuda_runtime.h>
#include <cuda_bf16.h>
#include <cstdint>

#define HWTOT 9216
#define NBAT  2
#define CIN   128
#define CE    64
#define BM    128
#define BN    64
#define NITER (HWTOT / BN)   // 144

// ---------------- bf16 split scratch (device globals) ----------------
__device__ __nv_bfloat16 g_Qh[NBAT * HWTOT * CE];   // [n][i][c]
__device__ __nv_bfloat16 g_Ql[NBAT * HWTOT * CE];
__device__ __nv_bfloat16 g_Kh[NBAT * HWTOT * CE];   // [n][j][c]
__device__ __nv_bfloat16 g_Kl[NBAT * HWTOT * CE];
__device__ __nv_bfloat16 g_Vh[NBAT * CIN * HWTOT];  // [n][c][j]
__device__ __nv_bfloat16 g_Vl[NBAT * CIN * HWTOT];

// ---------------- helpers (plain PTX ISA only — no 'a' features) ----------------
__device__ __forceinline__ uint32_t smem_u32(const void* p) {
    uint32_t a;
    asm("{ .reg .u64 t; cvta.to.shared.u64 t, %1; cvt.u32.u64 %0, t; }" : "=r"(a) : "l"(p));
    return a;
}
__device__ __forceinline__ uint32_t swz(uint32_t x) { return x ^ ((x >> 3) & 0x70); }

#define CVT_BF16X2(r, a, b) \
    asm("cvt.rn.satfinite.bf16x2.f32 %0, %1, %2;" : "=r"(r) : "f"(b), "f"(a))  // low=a, high=b

#define CP_ASYNC16(d, s)  asm volatile("cp.async.cg.shared.global [%0], [%1], 16;" :: "r"(d), "l"(s) : "memory")
#define CP_COMMIT()       asm volatile("cp.async.commit_group;" ::: "memory")
#define CP_WAIT0()        asm volatile("cp.async.wait_group 0;" ::: "memory")

#define LDSM4(r0, r1, r2, r3, a) \
    asm volatile("ldmatrix.sync.aligned.m8n8.x4.shared.b16 {%0,%1,%2,%3}, [%4];" \
        : "=r"(r0), "=r"(r1), "=r"(r2), "=r"(r3) : "r"(a) : "memory")

#define MMA_BF16(d, a, b0, b1) \
    asm volatile("mma.sync.aligned.m16n8k16.row.col.f32.bf16.bf16.f32 " \
        "{%0,%1,%2,%3}, {%4,%5,%6,%7}, {%8,%9}, {%0,%1,%2,%3};" \
        : "+f"((d)[0]), "+f"((d)[1]), "+f"((d)[2]), "+f"((d)[3]) \
        : "r"((a)[0]), "r"((a)[1]), "r"((a)[2]), "r"((a)[3]), "r"(b0), "r"(b1))

// ---------------------------------------------------------------------------
// Projection (x-tile loaded ONCE per block): grid (72, 2), 256 threads.
// Loops 8 row-groups; weight chunk staged per group; staging buffer reused
// for the Q/K transpose.
// ---------------------------------------------------------------------------
#define PROJ_XS_F   (128 * 128)          // x tile  [c][h]
#define PROJ_WS_F   (32 * 132)           // weight chunk / transpose staging
#define PROJ_SMEM   ((PROJ_XS_F + PROJ_WS_F) * 4)

__global__ void __launch_bounds__(256, 2) proj_kernel(
    const float* __restrict__ x,
    const float* __restrict__ w1, const float* __restrict__ b1, const float* __restrict__ a1,
    const float* __restrict__ w2, const float* __restrict__ b2, const float* __restrict__ a2,
    const float* __restrict__ wa, const float* __restrict__ ba, const float* __restrict__ aa)
{
    extern __shared__ float sm[];
    float* xs = sm;              // [128][128]
    float* ws = sm + PROJ_XS_F;  // [32][128] weights; then [32][132] staging

    const int n   = blockIdx.y;
    const int hw0 = blockIdx.x * 128;
    const int tid = threadIdx.x;
    const int w    = tid >> 5;
    const int lane = tid & 31;

    // Load x tile once
    for (int idx = tid * 4; idx < 128 * 128; idx += 1024) {
        int c = idx >> 7, h = idx & 127;
        *(float4*)&xs[idx] = *(const float4*)&x[(n * CIN + c) * HWTOT + hw0 + h];
    }

    for (int rg = 0; rg < 8; rg++) {
        const int rbase = rg * 32;
        const float* W; const float* B; const float* A; int cls;
        if (rbase < 64)       { W = w1 + rbase * CIN;          B = b1 + rbase;          A = a1; cls = 0; }
        else if (rbase < 128) { W = w2 + (rbase - 64) * CIN;   B = b2 + (rbase - 64);   A = a2; cls = 1; }
        else                  { W = wa + (rbase - 128) * CIN;  B = ba + (rbase - 128);  A = aa; cls = 2; }

        __syncthreads();   // prior staging reads (and iter-0 nothing) complete
        for (int idx = tid * 4; idx < 32 * 128; idx += 1024)
            *(float4*)&ws[idx] = *(const float4*)&W[idx];
        __syncthreads();   // ws + (iter 0) xs ready

        float acc[4][4];
#pragma unroll
        for (int r = 0; r < 4; r++)
#pragma unroll
            for (int q = 0; q < 4; q++) acc[r][q] = 0.f;

#pragma unroll 4
        for (int c = 0; c < CIN; c++) {
            float4 xv = *(float4*)&xs[c * 128 + 4 * lane];
#pragma unroll
            for (int rr = 0; rr < 4; rr++) {
                float wv = ws[(4 * w + rr) * 128 + c];
                acc[rr][0] += wv * xv.x;
                acc[rr][1] += wv * xv.y;
                acc[rr][2] += wv * xv.z;
                acc[rr][3] += wv * xv.w;
            }
        }

        const float slope = A[0];
        float y[4][4];
#pragma unroll
        for (int rr = 0; rr < 4; rr++) {
            const float bias = B[4 * w + rr];
#pragma unroll
            for (int q = 0; q < 4; q++) {
                float v = acc[rr][q] + bias;
                y[rr][q] = (v >= 0.f) ? v : slope * v;
            }
        }

        if (cls == 2) {
            // V: [c][j], bf16 2-term split, direct stores
#pragma unroll
            for (int rr = 0; rr < 4; rr++) {
                const int R  = rbase - 128 + 4 * w + rr;
                const int hw = hw0 + 4 * lane;
                uint32_t h01, h23, l01, l23;
                CVT_BF16X2(h01, y[rr][0], y[rr][1]);
                CVT_BF16X2(h23, y[rr][2], y[rr][3]);
                float hf0 = __uint_as_float(h01 << 16), hf1 = __uint_as_float(h01 & 0xffff0000u);
                float hf2 = __uint_as_float(h23 << 16), hf3 = __uint_as_float(h23 & 0xffff0000u);
                CVT_BF16X2(l01, y[rr][0] - hf0, y[rr][1] - hf1);
                CVT_BF16X2(l23, y[rr][2] - hf2, y[rr][3] - hf3);
                size_t off = (size_t)(n * CIN + R) * HWTOT + hw;
                *(uint2*)((char*)g_Vh + off * 2) = make_uint2(h01, h23);
                *(uint2*)((char*)g_Vl + off * 2) = make_uint2(l01, l23);
            }
        } else {
            // Q/K: transpose to [hw][c] via staging (reusing ws buffer)
            __syncthreads();   // everyone done reading ws as weights
#pragma unroll
            for (int rr = 0; rr < 4; rr++)
#pragma unroll
                for (int q = 0; q < 4; q++)
                    ws[(4 * w + rr) * 132 + 4 * lane + q] = y[rr][q];
            __syncthreads();   // staging ready

            const int h    = tid >> 1;
            const int half = tid & 1;
            float f[16];
#pragma unroll
            for (int k = 0; k < 16; k++)
                f[k] = ws[(16 * half + k) * 132 + h];

            uint32_t hp[8], lp[8];
#pragma unroll
            for (int p = 0; p < 8; p++) {
                uint32_t hh;
                CVT_BF16X2(hh, f[2 * p], f[2 * p + 1]);
                float h0 = __uint_as_float(hh << 16);
                float h1 = __uint_as_float(hh & 0xffff0000u);
                uint32_t ll;
                CVT_BF16X2(ll, f[2 * p] - h0, f[2 * p + 1] - h1);
                hp[p] = hh; lp[p] = ll;
            }
            const int col = ((cls == 0) ? rbase : rbase - 64) + 16 * half;
            size_t off = (size_t)(n * HWTOT + hw0 + h) * CE + col;
            __nv_bfloat16* dh = (cls == 0 ? g_Qh : g_Kh) + off;
            __nv_bfloat16* dl = (cls == 0 ? g_Ql : g_Kl) + off;
            *(uint4*)dh       = make_uint4(hp[0], hp[1], hp[2], hp[3]);
            *(uint4*)(dh + 8) = make_uint4(hp[4], hp[5], hp[6], hp[7]);
            *(uint4*)dl       = make_uint4(lp[0], lp[1], lp[2], lp[3]);
            *(uint4*)(dl + 8) = make_uint4(lp[4], lp[5], lp[6], lp[7]);
        }
    }
}

// ---------------------------------------------------------------------------
// mma.sync flash attention (max-free softmax) — exact R8 configuration.
// Grid (72,2), 256 threads. Warp w owns rows 16w..16w+15; Q frags persistent.
// QK: bf16 3-term (hh+hl+lh). PV: PhVh + PhVl + PlVh.
// ---------------------------------------------------------------------------
#define OFF_QH 0
#define OFF_QL 16384
#define OFF_KH 32768     // [2][8192]
#define OFF_KL 49152
#define OFF_VH 65536     // [2][16384]
#define OFF_VL 98304
#define ATTN_SMEM 131072

__global__ void __launch_bounds__(256, 1) attn_kernel(float* __restrict__ out)
{
    extern __shared__ char smem[];
    const uint32_t sb = smem_u32(smem);

    const int n    = blockIdx.y;
    const int i0   = blockIdx.x * BM;
    const int tid  = threadIdx.x;
    const int wid  = tid >> 5;
    const int lane = tid & 31;
    const int m0   = wid * 16;

    // ---- Prologue: Q (persistent) + KV tile 0 ----
    {
        const char* qh = (const char*)g_Qh + (size_t)(n * HWTOT + i0) * CE * 2;
        const char* ql = (const char*)g_Ql + (size_t)(n * HWTOT + i0) * CE * 2;
        for (int i = tid; i < 1024; i += 256) {
            CP_ASYNC16(sb + OFF_QH + swz(i * 16), qh + (size_t)i * 16);
            CP_ASYNC16(sb + OFF_QL + swz(i * 16), ql + (size_t)i * 16);
        }
        const char* kh = (const char*)g_Kh + (size_t)(n * HWTOT) * CE * 2;
        const char* kl = (const char*)g_Kl + (size_t)(n * HWTOT) * CE * 2;
        for (int i = tid; i < 512; i += 256) {
            CP_ASYNC16(sb + OFF_KH + swz(i * 16), kh + (size_t)i * 16);
            CP_ASYNC16(sb + OFF_KL + swz(i * 16), kl + (size_t)i * 16);
        }
        const char* vh = (const char*)g_Vh + (size_t)n * CIN * HWTOT * 2;
        const char* vl = (const char*)g_Vl + (size_t)n * CIN * HWTOT * 2;
        for (int i = tid; i < 1024; i += 256) {
            int c = i >> 3, cb = (i & 7) * 16;
            CP_ASYNC16(sb + OFF_VH + swz(i * 16), vh + (size_t)c * HWTOT * 2 + cb);
            CP_ASYNC16(sb + OFF_VL + swz(i * 16), vl + (size_t)c * HWTOT * 2 + cb);
        }
        CP_COMMIT();
    }
    CP_WAIT0();
    __syncthreads();

    // ---- Load Q fragments (A, m16k16 per kstep) ----
    uint32_t qh[4][4], ql[4][4];
    {
        const int mrow = (lane & 7) + ((lane >> 3) & 1) * 8;
        const int cb   = (lane >> 4) * 16;
#pragma unroll
        for (int s = 0; s < 4; s++) {
            uint32_t a = sb + OFF_QH + swz((uint32_t)(m0 + mrow) * 128 + s * 32 + cb);
            LDSM4(qh[s][0], qh[s][1], qh[s][2], qh[s][3], a);
            a = sb + OFF_QL + swz((uint32_t)(m0 + mrow) * 128 + s * 32 + cb);
            LDSM4(ql[s][0], ql[s][1], ql[s][2], ql[s][3], a);
        }
    }

    float o[16][4];
#pragma unroll
    for (int i = 0; i < 16; i++)
#pragma unroll
        for (int q = 0; q < 4; q++) o[i][q] = 0.f;
    float lacc0 = 0.f, lacc1 = 0.f;

    const int brow = lane & 7;
    const int bcb  = (lane >> 3) * 16;

    for (int t = 0; t < NITER; t++) {
        const int buf = t & 1;
        if (t) { CP_WAIT0(); }
        __syncthreads();

        // Prefetch KV(t+1)
        if (t + 1 < NITER) {
            const int nb = (t + 1) & 1;
            const int j1 = (t + 1) * BN;
            const char* kh = (const char*)g_Kh + (size_t)(n * HWTOT + j1) * CE * 2;
            const char* kl = (const char*)g_Kl + (size_t)(n * HWTOT + j1) * CE * 2;
            for (int i = tid; i < 512; i += 256) {
                CP_ASYNC16(sb + OFF_KH + nb * 8192 + swz(i * 16), kh + (size_t)i * 16);
                CP_ASYNC16(sb + OFF_KL + nb * 8192 + swz(i * 16), kl + (size_t)i * 16);
            }
            const char* vh = (const char*)g_Vh + ((size_t)n * CIN * HWTOT + j1) * 2;
            const char* vl = (const char*)g_Vl + ((size_t)n * CIN * HWTOT + j1) * 2;
            for (int i = tid; i < 1024; i += 256) {
                int c = i >> 3, cb2 = (i & 7) * 16;
                CP_ASYNC16(sb + OFF_VH + nb * 16384 + swz(i * 16), vh + (size_t)c * HWTOT * 2 + cb2);
                CP_ASYNC16(sb + OFF_VL + nb * 16384 + swz(i * 16), vl + (size_t)c * HWTOT * 2 + cb2);
            }
            CP_COMMIT();
        }

        // ---- QK + exp + pack: S strip m16 x 64 ----
        const uint32_t kbh = sb + OFF_KH + buf * 8192;
        const uint32_t kbl = sb + OFF_KL + buf * 8192;
        uint32_t ph[4][4], pl[4][4];

#pragma unroll
        for (int nt = 0; nt < 8; nt++) {
            uint32_t bh[8], bl[8];
            const uint32_t o0 = swz((uint32_t)(nt * 8 + brow) * 128 + bcb);
            const uint32_t o1 = swz((uint32_t)(nt * 8 + brow) * 128 + bcb + 64);
            LDSM4(bh[0], bh[1], bh[2], bh[3], kbh + o0);
            LDSM4(bh[4], bh[5], bh[6], bh[7], kbh + o1);
            LDSM4(bl[0], bl[1], bl[2], bl[3], kbl + o0);
            LDSM4(bl[4], bl[5], bl[6], bl[7], kbl + o1);

            float sc[4] = {0.f, 0.f, 0.f, 0.f};
#pragma unroll
            for (int ks = 0; ks < 4; ks++) {
                MMA_BF16(sc, qh[ks], bh[2 * ks], bh[2 * ks + 1]);
                MMA_BF16(sc, qh[ks], bl[2 * ks], bl[2 * ks + 1]);
                MMA_BF16(sc, ql[ks], bh[2 * ks], bh[2 * ks + 1]);
            }

            float e0 = __expf(sc[0]), e1 = __expf(sc[1]);
            float e2 = __expf(sc[2]), e3 = __expf(sc[3]);
            lacc0 += e0 + e1;
            lacc1 += e2 + e3;
            uint32_t h01, h23;
            CVT_BF16X2(h01, e0, e1);
            CVT_BF16X2(h23, e2, e3);
            float r0 = e0 - __uint_as_float(h01 << 16);
            float r1 = e1 - __uint_as_float(h01 & 0xffff0000u);
            float r2 = e2 - __uint_as_float(h23 << 16);
            float r3 = e3 - __uint_as_float(h23 & 0xffff0000u);
            uint32_t l01, l23;
            CVT_BF16X2(l01, r0, r1);
            CVT_BF16X2(l23, r2, r3);
            const int ks2 = nt >> 1, sl = (nt & 1) * 2;
            ph[ks2][sl] = h01; ph[ks2][sl + 1] = h23;
            pl[ks2][sl] = l01; pl[ks2][sl + 1] = l23;
        }

        // ---- PV: O += P V ----
        const uint32_t vbh = sb + OFF_VH + buf * 16384;
        const uint32_t vbl = sb + OFF_VL + buf * 16384;
#pragma unroll
        for (int nt2 = 0; nt2 < 16; nt2++) {
            uint32_t bh[8], bl[8];
            const uint32_t o0 = swz((uint32_t)(nt2 * 8 + brow) * 128 + bcb);
            const uint32_t o1 = swz((uint32_t)(nt2 * 8 + brow) * 128 + bcb + 64);
            LDSM4(bh[0], bh[1], bh[2], bh[3], vbh + o0);
            LDSM4(bh[4], bh[5], bh[6], bh[7], vbh + o1);
            LDSM4(bl[0], bl[1], bl[2], bl[3], vbl + o0);
            LDSM4(bl[4], bl[5], bl[6], bl[7], vbl + o1);
#pragma unroll
            for (int ks = 0; ks < 4; ks++) {
                MMA_BF16(o[nt2], ph[ks], bh[2 * ks], bh[2 * ks + 1]);
                MMA_BF16(o[nt2], ph[ks], bl[2 * ks], bl[2 * ks + 1]);
                MMA_BF16(o[nt2], pl[ks], bh[2 * ks], bh[2 * ks + 1]);
            }
        }
    }

    // ---- Epilogue ----
    lacc0 += __shfl_xor_sync(0xffffffffu, lacc0, 1);
    lacc0 += __shfl_xor_sync(0xffffffffu, lacc0, 2);
    lacc1 += __shfl_xor_sync(0xffffffffu, lacc1, 1);
    lacc1 += __shfl_xor_sync(0xffffffffu, lacc1, 2);
    const float inv0 = 1.f / lacc0;
    const float inv1 = 1.f / lacc1;
    const int r0 = i0 + m0 + (lane >> 2);
#pragma unroll
    for (int nt2 = 0; nt2 < 16; nt2++) {
        const int c = nt2 * 8 + (lane & 3) * 2;
        out[(size_t)(n * CIN + c) * HWTOT + r0]         = o[nt2][0] * inv0;
        out[(size_t)(n * CIN + c + 1) * HWTOT + r0]     = o[nt2][1] * inv0;
        out[(size_t)(n * CIN + c) * HWTOT + r0 + 8]     = o[nt2][2] * inv1;
        out[(size_t)(n * CIN + c + 1) * HWTOT + r0 + 8] = o[nt2][3] * inv1;
    }
}

extern "C" void kernel_launch(void* const* d_in, const int* in_sizes, int n_in,
                              void* d_out, int out_size)
{
    const float* x  = (const float*)d_in[0];
    const float* w1 = (const float*)d_in[1];
    const float* b1 = (const float*)d_in[2];
    const float* a1 = (const float*)d_in[3];
    const float* w2 = (const float*)d_in[4];
    const float* b2 = (const float*)d_in[5];
    const float* a2 = (const float*)d_in[6];
    const float* wa = (const float*)d_in[7];
    const float* ba = (const float*)d_in[8];
    const float* aa = (const float*)d_in[9];
    float* out = (float*)d_out;

    cudaFuncSetAttribute(proj_kernel, cudaFuncAttributeMaxDynamicSharedMemorySize, PROJ_SMEM);
    cudaFuncSetAttribute(attn_kernel, cudaFuncAttributeMaxDynamicSharedMemorySize, ATTN_SMEM);

    proj_kernel<<<dim3(HWTOT / 128, NBAT), 256, PROJ_SMEM>>>(
        x, w1, b1, a1, w2, b2, a2, wa, ba, aa);
    attn_kernel<<<dim3(HWTOT / BM, NBAT), 256, ATTN_SMEM>>>(out);
}